// round 7
// baseline (speedup 1.0000x reference)
#include <cuda_runtime.h>
#include <cuda_bf16.h>
#include <math.h>
#include <stdint.h>

// Problem constants
#define BB   1024
#define DM   512
#define NH   8
#define HD   64
#define NN   81
#define OC   1536

// GEMM tiling (int8: K per stage doubled, same byte geometry as bf16 version)
#define MT     128          // o rows per CTA
#define NT     96           // padded n (81 -> 96)
#define KT     64           // k (int8 elems) per pipeline stage = 64 bytes/row
#define NTILES (DM / KT)    // 8
#define NSTG   3

#define RSTRIDE 80          // 64B data + 16B pad per row
#define APL  (MT * RSTRIDE)
#define BPL  (NT * RSTRIDE)
#define ASTG (2 * APL)
#define BSTG (2 * BPL)
#define STG_BYTES (ASTG + BSTG)
#define SMEM_GEMM (NSTG * STG_BYTES)   // 107520

#define QMAX 32256.0f       // int16 quant range (keeps hi limb in [-126,126])

// Scratch
__device__ float    g_qkv[(size_t)BB * OC * NN];
__device__ int8_t   g_wh[(size_t)OC * DM];
__device__ int8_t   g_wl[(size_t)OC * DM];
__device__ int8_t   g_xh[(size_t)BB * NT * DM];
__device__ int8_t   g_xl[(size_t)BB * NT * DM];
__device__ unsigned g_amax[2];   // float bits of amax(|w|), amax(|x|)

__device__ __forceinline__ uint32_t smem_u32(const void* p) {
    uint32_t a;
    asm("{ .reg .u64 t; cvta.to.shared.u64 t, %1; cvt.u32.u64 %0, t; }" : "=r"(a) : "l"(p));
    return a;
}

#define CP16(dst, src) \
    asm volatile("cp.async.cg.shared.global [%0], [%1], 16;" :: "r"(dst), "l"(src))
#define CP_COMMIT() asm volatile("cp.async.commit_group;" ::: "memory")
#define CP_WAIT(n)  asm volatile("cp.async.wait_group %0;" :: "n"(n) : "memory")

#define LDSM4(r0, r1, r2, r3, addr)                                           \
    asm volatile("ldmatrix.sync.aligned.m8n8.x4.shared.b16 {%0,%1,%2,%3}, [%4];" \
        : "=r"(r0), "=r"(r1), "=r"(r2), "=r"(r3) : "r"(addr))

#define MMA_S8(C, A, B)                                                       \
    asm volatile(                                                             \
        "mma.sync.aligned.m16n8k32.row.col.s32.s8.s8.s32 "                    \
        "{%0,%1,%2,%3}, {%4,%5,%6,%7}, {%8,%9}, {%0,%1,%2,%3};\n"             \
        : "+r"((C)[0]), "+r"((C)[1]), "+r"((C)[2]), "+r"((C)[3])              \
        : "r"((A)[0]), "r"((A)[1]), "r"((A)[2]), "r"((A)[3]),                 \
          "r"((B)[0]), "r"((B)[1]))

// split int16 value into hi/lo int8 limbs (round-half-up on hi)
__device__ __forceinline__ void limbs(float v, float inv, int8_t& h, int8_t& l) {
    int X = __float2int_rn(v * inv);
    X = max(-32256, min(32256, X));
    int Xh = (X + 128) >> 8;
    h = (int8_t)Xh;
    l = (int8_t)(X - (Xh << 8));
}

// ---------------------------------------------------------------------------
// amax reduction kernels
// ---------------------------------------------------------------------------
__global__ void zero_amax() {
    if (threadIdx.x < 2) g_amax[threadIdx.x] = 0u;
}

__global__ void amax_kernel(const float* __restrict__ p, size_t n, int slot) {
    size_t i = (size_t)blockIdx.x * blockDim.x + threadIdx.x;
    size_t stride = (size_t)gridDim.x * blockDim.x;
    float m = 0.0f;
    for (; i < n; i += stride) m = fmaxf(m, fabsf(p[i]));
#pragma unroll
    for (int s = 16; s > 0; s >>= 1)
        m = fmaxf(m, __shfl_xor_sync(0xFFFFFFFF, m, s));
    if ((threadIdx.x & 31) == 0)
        atomicMax(&g_amax[slot], __float_as_uint(m));
}

// ---------------------------------------------------------------------------
// Prep: quantize W -> int8 limb planes, layout [o][c]
// ---------------------------------------------------------------------------
__global__ void prep_w(const float* __restrict__ w) {
    int i = blockIdx.x * 256 + threadIdx.x;
    float inv = QMAX / __uint_as_float(g_amax[0]);
    int8_t h, l;
    limbs(w[i], inv, h, l);
    g_wh[i] = h;
    g_wl[i] = l;
}

// ---------------------------------------------------------------------------
// Prep: transpose + quantize X -> [b][n(96)][c(512)] limb planes (n>=81 zero)
// ---------------------------------------------------------------------------
__global__ __launch_bounds__(256) void prep_x(const float* __restrict__ x) {
    __shared__ float ts[64][83];
    const int b  = blockIdx.x;
    const int c0 = blockIdx.y * 64;
    const int tid = threadIdx.x;
    const float inv = QMAX / __uint_as_float(g_amax[1]);

    const float* xb = x + ((size_t)b * DM + c0) * NN;
    for (int idx = tid; idx < 64 * NN; idx += 256) {
        int c = idx / NN;
        int n = idx - c * NN;
        ts[c][n] = xb[(size_t)c * NN + n];
    }
    __syncthreads();

    for (int idx = tid; idx < NT * 64; idx += 256) {
        int n = idx >> 6;
        int c = idx & 63;
        float v = (n < NN) ? ts[c][n] : 0.0f;
        int8_t h, l;
        limbs(v, inv, h, l);
        size_t dst = ((size_t)b * NT + n) * DM + c0 + c;
        g_xh[dst] = h;
        g_xl[dst] = l;
    }
}

// ---------------------------------------------------------------------------
// Stage loader: cp.async 16B chunks into [Ah | Al | Bh | Bl] for one K tile
// ---------------------------------------------------------------------------
__device__ __forceinline__ void load_stage(uint32_t sb, int stage, int k0,
                                           int o0, int b, int tid) {
    const uint32_t base = sb + stage * STG_BYTES;
#pragma unroll
    for (int i = 0; i < 4; i++) {               // A: 1024 chunks
        int idx   = tid + i * 256;
        int plane = idx >> 9;
        int r     = idx & 511;
        int row   = r >> 2;
        int chv   = r & 3;
        const int8_t* src =
            (plane ? g_wl : g_wh) + (size_t)(o0 + row) * DM + k0 + chv * 16;
        CP16(base + plane * APL + row * RSTRIDE + chv * 16, src);
    }
#pragma unroll
    for (int i = 0; i < 3; i++) {               // B: 768 chunks
        int idx   = tid + i * 256;
        int plane = idx >= 384;
        int r     = plane ? idx - 384 : idx;
        int row   = r >> 2;
        int chv   = r & 3;
        const int8_t* src =
            (plane ? g_xl : g_xh) + ((size_t)b * NT + row) * DM + k0 + chv * 16;
        CP16(base + ASTG + plane * BPL + row * RSTRIDE + chv * 16, src);
    }
    CP_COMMIT();
}

// ---------------------------------------------------------------------------
// Kernel 1: QKV GEMM, 2-limb int8, IMMA m16n8k32, cp.async 3-stage pipeline
// 8 warps = 4(M) x 2(N); warp tile 32 x 48.
//   P1 = sum XhYh ; P2 = sum (XhYl + XlYh) ; out = s^2(65536 P1 + 256 P2)
// ---------------------------------------------------------------------------
__global__ __launch_bounds__(256) void qkv_gemm_imma(const float* __restrict__ bias) {
    extern __shared__ char smem[];
    const uint32_t sb = smem_u32(smem);
    const int tid  = threadIdx.x;
    const int o0   = blockIdx.x * MT;
    const int b    = blockIdx.y;
    const int warp = tid >> 5;
    const int lane = tid & 31;
    const int wm   = warp & 3;
    const int wn   = warp >> 2;
    const int g    = lane >> 2;
    const int l4   = lane & 3;

    const uint32_t aoff = ((lane & 7) + ((lane >> 3) & 1) * 8) * RSTRIDE + (lane >> 4) * 16;
    const uint32_t boff = ((lane & 7) + ((lane >> 4) & 1) * 8) * RSTRIDE + ((lane >> 3) & 1) * 16;

    int P1[2][6][4], P2[2][6][4];
#pragma unroll
    for (int i = 0; i < 2; i++)
#pragma unroll
        for (int j = 0; j < 6; j++)
#pragma unroll
            for (int r = 0; r < 4; r++) { P1[i][j][r] = 0; P2[i][j][r] = 0; }

    load_stage(sb, 0, 0, o0, b, tid);
    load_stage(sb, 1, KT, o0, b, tid);

    for (int ch = 0; ch < NTILES; ch++) {
        if (ch + NSTG - 1 < NTILES) { CP_WAIT(1); } else { CP_WAIT(0); }
        __syncthreads();
        if (ch + NSTG - 1 < NTILES)
            load_stage(sb, (ch + NSTG - 1) % NSTG, (ch + NSTG - 1) * KT, o0, b, tid);

        const uint32_t st  = sb + (ch % NSTG) * STG_BYTES;
        const uint32_t sAh = st;
        const uint32_t sAl = st + APL;
        const uint32_t sBh = st + ASTG;
        const uint32_t sBl = sBh + BPL;

#pragma unroll
        for (int ks = 0; ks < 2; ks++) {        // two k32 steps per stage
            uint32_t ah[2][4], al[2][4];
#pragma unroll
            for (int mi = 0; mi < 2; mi++) {
                uint32_t ra = (uint32_t)((wm * 32 + mi * 16) * RSTRIDE + ks * 32) + aoff;
                LDSM4(ah[mi][0], ah[mi][1], ah[mi][2], ah[mi][3], sAh + ra);
                LDSM4(al[mi][0], al[mi][1], al[mi][2], al[mi][3], sAl + ra);
            }
            uint32_t bh[3][4], bl[3][4];
#pragma unroll
            for (int pr = 0; pr < 3; pr++) {
                uint32_t rb = (uint32_t)((wn * 48 + pr * 16) * RSTRIDE + ks * 32) + boff;
                LDSM4(bh[pr][0], bh[pr][1], bh[pr][2], bh[pr][3], sBh + rb);
                LDSM4(bl[pr][0], bl[pr][1], bl[pr][2], bl[pr][3], sBl + rb);
            }
            // batch 1: P1 += Ah*Bh (12 independent)
#pragma unroll
            for (int pr = 0; pr < 3; pr++)
#pragma unroll
                for (int sub = 0; sub < 2; sub++)
#pragma unroll
                    for (int mi = 0; mi < 2; mi++)
                        MMA_S8(P1[mi][pr * 2 + sub], ah[mi], bh[pr] + sub * 2);
            // batch 2: P2 += Ah*Bl
#pragma unroll
            for (int pr = 0; pr < 3; pr++)
#pragma unroll
                for (int sub = 0; sub < 2; sub++)
#pragma unroll
                    for (int mi = 0; mi < 2; mi++)
                        MMA_S8(P2[mi][pr * 2 + sub], ah[mi], bl[pr] + sub * 2);
            // batch 3: P2 += Al*Bh (dependent on batch 2, distance 12)
#pragma unroll
            for (int pr = 0; pr < 3; pr++)
#pragma unroll
                for (int sub = 0; sub < 2; sub++)
#pragma unroll
                    for (int mi = 0; mi < 2; mi++)
                        MMA_S8(P2[mi][pr * 2 + sub], al[mi], bh[pr] + sub * 2);
        }
    }

    // ---- Epilogue: combine limbs, scale, bias, fp32 stores ----
    const float sw = __uint_as_float(g_amax[0]) * (1.0f / QMAX);
    const float sx = __uint_as_float(g_amax[1]) * (1.0f / QMAX);
    const float s2 = sw * sx;

#pragma unroll
    for (int mi = 0; mi < 2; mi++) {
        const int oa = o0 + wm * 32 + mi * 16 + g;
        const float bva = bias[oa];
        const float bvb = bias[oa + 8];
        float* da = g_qkv + ((size_t)b * OC + oa) * NN;
        float* db = da + (size_t)8 * NN;
#pragma unroll
        for (int f = 0; f < 6; f++) {
            const int n = wn * 48 + f * 8 + 2 * l4;
            float v0 = (65536.0f * (float)P1[mi][f][0] + 256.0f * (float)P2[mi][f][0]) * s2 + bva;
            float v1 = (65536.0f * (float)P1[mi][f][1] + 256.0f * (float)P2[mi][f][1]) * s2 + bva;
            float v2 = (65536.0f * (float)P1[mi][f][2] + 256.0f * (float)P2[mi][f][2]) * s2 + bvb;
            float v3 = (65536.0f * (float)P1[mi][f][3] + 256.0f * (float)P2[mi][f][3]) * s2 + bvb;
            if (n < NN)     { da[n]     = v0; db[n]     = v2; }
            if (n + 1 < NN) { da[n + 1] = v1; db[n + 1] = v3; }
        }
    }
}

// ---------------------------------------------------------------------------
// Kernel 2: attention per (b, h) — fp32.
// ---------------------------------------------------------------------------
#define QP 65
#define SP 83
__global__ __launch_bounds__(256) void attn_kernel(const float* __restrict__ rel_h,
                                                   const float* __restrict__ rel_w,
                                                   float* __restrict__ out) {
    extern __shared__ float sm[];
    float* Qs = sm;
    float* Ks = sm + NN * QP;
    float* S  = sm + 2 * NN * QP;

    const int bh = blockIdx.x;
    const int b  = bh >> 3;
    const int h  = bh & 7;
    const int tid = threadIdx.x;

    const float* qkvb = g_qkv + (size_t)b * OC * NN;
    const float* Qg = qkvb + (size_t)(h * HD) * NN;
    const float* Kg = qkvb + (size_t)(DM + h * HD) * NN;
    const float* Vg = qkvb + (size_t)(2 * DM + h * HD) * NN;

    for (int idx = tid; idx < HD * NN; idx += 256) {
        int d = idx / NN;
        int n = idx % NN;
        Qs[n * QP + d] = Qg[d * NN + n];
        float rh = rel_h[(h * HD + d) * 9 + (n % 9)];
        float rw = rel_w[(h * HD + d) * 9 + (n / 9)];
        Ks[n * QP + d] = Kg[d * NN + n] + rh + rw;
    }
    __syncthreads();

    for (int idx = tid; idx < NN * NN; idx += 256) {
        int n = idx / NN;
        int m = idx % NN;
        const float* qp = Qs + n * QP;
        const float* kp = Ks + m * QP;
        float s = 0.0f;
#pragma unroll
        for (int d = 0; d < HD; d++) s += qp[d] * kp[d];
        S[n * SP + m] = s;
    }
    __syncthreads();

    for (int idx = tid; idx < HD * NN; idx += 256) {
        int d = idx / NN;
        int n = idx % NN;
        Ks[n * QP + d] = Vg[d * NN + n];
    }
    if (tid < NN) {
        float* row = S + tid * SP;
        float mx = row[0];
        for (int m = 1; m < NN; m++) mx = fmaxf(mx, row[m]);
        float sum = 0.0f;
        for (int m = 0; m < NN; m++) {
            float e = __expf(row[m] - mx);
            row[m] = e;
            sum += e;
        }
        float inv = 1.0f / sum;
        for (int m = 0; m < NN; m++) row[m] *= inv;
    }
    __syncthreads();

    for (int idx = tid; idx < HD * NN; idx += 256) {
        int d = idx / NN;
        int n = idx % NN;
        const float* pr = S + n * SP;
        float acc = 0.0f;
#pragma unroll
        for (int m = 0; m < NN; m++) acc += pr[m] * Ks[m * QP + d];
        out[((size_t)b * DM + h * HD + d) * NN + n] = acc;
    }
}

// ---------------------------------------------------------------------------
extern "C" void kernel_launch(void* const* d_in, const int* in_sizes, int n_in,
                              void* d_out, int out_size) {
    const float* x     = (const float*)d_in[0];
    const float* qkv_w = (const float*)d_in[1];
    const float* qkv_b = (const float*)d_in[2];
    const float* rel_h = (const float*)d_in[3];
    const float* rel_w = (const float*)d_in[4];
    float* out = (float*)d_out;

    static const int SMEM_ATTN = (2 * NN * QP + NN * SP) * sizeof(float);
    cudaFuncSetAttribute(attn_kernel, cudaFuncAttributeMaxDynamicSharedMemorySize, SMEM_ATTN);
    cudaFuncSetAttribute(qkv_gemm_imma, cudaFuncAttributeMaxDynamicSharedMemorySize, SMEM_GEMM);

    zero_amax<<<1, 32>>>();
    amax_kernel<<<256, 256>>>(qkv_w, (size_t)OC * DM, 0);
    amax_kernel<<<2048, 256>>>(x, (size_t)BB * DM * NN, 1);
    prep_w<<<OC * DM / 256, 256>>>(qkv_w);
    prep_x<<<dim3(BB, DM / 64), 256>>>(x);
    qkv_gemm_imma<<<dim3(OC / MT, BB), 256, SMEM_GEMM>>>(qkv_b);
    attn_kernel<<<BB * NH, 256, SMEM_ATTN>>>(rel_h, rel_w, out);
}

// round 8
// speedup vs baseline: 3.0613x; 3.0613x over previous
#include <cuda_runtime.h>
#include <cuda_fp16.h>
#include <math.h>
#include <stdint.h>

// Problem constants
#define BB   1024
#define DM   512
#define NH   8
#define HD   64
#define NN   81
#define OC   1536

// GEMM tiling (fp16 single plane)
#define MT     128          // o rows per CTA
#define NT     96           // padded n (81 -> 96)
#define KT     32           // k per pipeline stage (64B rows)
#define NTILES (DM / KT)    // 16
#define NSTG   3

#define RSTRIDE 80          // 64B data + 16B pad per row (ldmatrix conflict-free)
#define APL  (MT * RSTRIDE)            // 10240
#define BPL  (NT * RSTRIDE)            // 7680
#define STG_BYTES (APL + BPL)          // 17920
#define SMEM_GEMM (NSTG * STG_BYTES)   // 53760

// Scratch
__device__ float  g_qkv[(size_t)BB * OC * NN];
__device__ __half g_wh[(size_t)OC * DM];
__device__ __half g_xh[(size_t)BB * NT * DM];

__device__ __forceinline__ uint32_t smem_u32(const void* p) {
    uint32_t a;
    asm("{ .reg .u64 t; cvta.to.shared.u64 t, %1; cvt.u32.u64 %0, t; }" : "=r"(a) : "l"(p));
    return a;
}

#define CP16(dst, src) \
    asm volatile("cp.async.cg.shared.global [%0], [%1], 16;" :: "r"(dst), "l"(src))
#define CP_COMMIT() asm volatile("cp.async.commit_group;" ::: "memory")
#define CP_WAIT(n)  asm volatile("cp.async.wait_group %0;" :: "n"(n) : "memory")

#define LDSM4(r0, r1, r2, r3, addr)                                           \
    asm volatile("ldmatrix.sync.aligned.m8n8.x4.shared.b16 {%0,%1,%2,%3}, [%4];" \
        : "=r"(r0), "=r"(r1), "=r"(r2), "=r"(r3) : "r"(addr))

#define MMA_F16(C, A, B)                                                      \
    asm volatile(                                                             \
        "mma.sync.aligned.m16n8k16.row.col.f32.f16.f16.f32 "                  \
        "{%0,%1,%2,%3}, {%4,%5,%6,%7}, {%8,%9}, {%0,%1,%2,%3};\n"             \
        : "+f"((C)[0]), "+f"((C)[1]), "+f"((C)[2]), "+f"((C)[3])              \
        : "r"((A)[0]), "r"((A)[1]), "r"((A)[2]), "r"((A)[3]),                 \
          "r"((B)[0]), "r"((B)[1]))

// ---------------------------------------------------------------------------
// Prep: W -> fp16, layout [o][c]
// ---------------------------------------------------------------------------
__global__ void prep_w(const float* __restrict__ w) {
    int i = blockIdx.x * 256 + threadIdx.x;
    g_wh[i] = __float2half_rn(w[i]);
}

// ---------------------------------------------------------------------------
// Prep: transpose X -> [b][n(96)][c(512)] fp16 (n>=81 zeroed)
// ---------------------------------------------------------------------------
__global__ __launch_bounds__(256) void prep_x(const float* __restrict__ x) {
    __shared__ float ts[64][83];
    const int b  = blockIdx.x;
    const int c0 = blockIdx.y * 64;
    const int tid = threadIdx.x;

    const float* xb = x + ((size_t)b * DM + c0) * NN;
    for (int idx = tid; idx < 64 * NN; idx += 256) {
        int c = idx / NN;
        int n = idx - c * NN;
        ts[c][n] = xb[(size_t)c * NN + n];
    }
    __syncthreads();

    for (int idx = tid; idx < NT * 64; idx += 256) {
        int n = idx >> 6;
        int c = idx & 63;
        float v = (n < NN) ? ts[c][n] : 0.0f;
        g_xh[((size_t)b * NT + n) * DM + c0 + c] = __float2half_rn(v);
    }
}

// ---------------------------------------------------------------------------
// Stage loader: cp.async 16B chunks into [A | B] for one K tile
// ---------------------------------------------------------------------------
__device__ __forceinline__ void load_stage(uint32_t sb, int stage, int k0,
                                           int o0, int b, int tid) {
    const uint32_t base = sb + stage * STG_BYTES;
#pragma unroll
    for (int i = 0; i < 2; i++) {               // A: 512 chunks
        int idx = tid + i * 256;
        int row = idx >> 2;
        int chv = idx & 3;
        const __half* src = g_wh + (size_t)(o0 + row) * DM + k0 + chv * 8;
        CP16(base + row * RSTRIDE + chv * 16, src);
    }
    {                                           // B: 384 chunks
        int idx = tid;
        int row = idx >> 2;
        int chv = idx & 3;
        const __half* src = g_xh + ((size_t)b * NT + row) * DM + k0 + chv * 8;
        CP16(base + APL + row * RSTRIDE + chv * 16, src);
        if (tid < 128) {
            idx = tid + 256;
            row = idx >> 2;
            chv = idx & 3;
            src = g_xh + ((size_t)b * NT + row) * DM + k0 + chv * 8;
            CP16(base + APL + row * RSTRIDE + chv * 16, src);
        }
    }
    CP_COMMIT();
}

// ---------------------------------------------------------------------------
// Kernel 1: QKV GEMM, fp16 HMMA, cp.async 3-stage pipeline
// 8 warps = 4(M) x 2(N); warp tile 32 x 48.
// ---------------------------------------------------------------------------
__global__ __launch_bounds__(256) void qkv_gemm_f16(const float* __restrict__ bias) {
    extern __shared__ char smem[];
    const uint32_t sb = smem_u32(smem);
    const int tid  = threadIdx.x;
    const int o0   = blockIdx.x * MT;
    const int b    = blockIdx.y;
    const int warp = tid >> 5;
    const int lane = tid & 31;
    const int wm   = warp & 3;
    const int wn   = warp >> 2;
    const int g    = lane >> 2;
    const int l4   = lane & 3;

    const uint32_t aoff = ((lane & 7) + ((lane >> 3) & 1) * 8) * RSTRIDE + (lane >> 4) * 16;
    const uint32_t boff = ((lane & 7) + ((lane >> 4) & 1) * 8) * RSTRIDE + ((lane >> 3) & 1) * 16;

    float acc[2][6][4];
#pragma unroll
    for (int i = 0; i < 2; i++)
#pragma unroll
        for (int j = 0; j < 6; j++)
#pragma unroll
            for (int r = 0; r < 4; r++) acc[i][j][r] = 0.0f;

    load_stage(sb, 0, 0, o0, b, tid);
    load_stage(sb, 1, KT, o0, b, tid);

    for (int ch = 0; ch < NTILES; ch++) {
        if (ch + NSTG - 1 < NTILES) { CP_WAIT(1); } else { CP_WAIT(0); }
        __syncthreads();
        if (ch + NSTG - 1 < NTILES)
            load_stage(sb, (ch + NSTG - 1) % NSTG, (ch + NSTG - 1) * KT, o0, b, tid);

        const uint32_t st = sb + (ch % NSTG) * STG_BYTES;
        const uint32_t sA = st;
        const uint32_t sB = st + APL;

#pragma unroll
        for (int ks = 0; ks < 2; ks++) {
            uint32_t a[2][4];
#pragma unroll
            for (int mi = 0; mi < 2; mi++) {
                uint32_t ra = (uint32_t)((wm * 32 + mi * 16) * RSTRIDE + ks * 32) + aoff;
                LDSM4(a[mi][0], a[mi][1], a[mi][2], a[mi][3], sA + ra);
            }
            uint32_t bf[3][4];
#pragma unroll
            for (int pr = 0; pr < 3; pr++) {
                uint32_t rb = (uint32_t)((wn * 48 + pr * 16) * RSTRIDE + ks * 32) + boff;
                LDSM4(bf[pr][0], bf[pr][1], bf[pr][2], bf[pr][3], sB + rb);
            }
#pragma unroll
            for (int pr = 0; pr < 3; pr++)
#pragma unroll
                for (int sub = 0; sub < 2; sub++)
#pragma unroll
                    for (int mi = 0; mi < 2; mi++)
                        MMA_F16(acc[mi][pr * 2 + sub], a[mi], bf[pr] + sub * 2);
        }
    }

    // ---- Epilogue: bias + fp32 stores ----
#pragma unroll
    for (int mi = 0; mi < 2; mi++) {
        const int oa = o0 + wm * 32 + mi * 16 + g;
        const float bva = bias[oa];
        const float bvb = bias[oa + 8];
        float* da = g_qkv + ((size_t)b * OC + oa) * NN;
        float* db = da + (size_t)8 * NN;
#pragma unroll
        for (int f = 0; f < 6; f++) {
            const int n = wn * 48 + f * 8 + 2 * l4;
            if (n < NN)     { da[n]     = acc[mi][f][0] + bva;
                              db[n]     = acc[mi][f][2] + bvb; }
            if (n + 1 < NN) { da[n + 1] = acc[mi][f][1] + bva;
                              db[n + 1] = acc[mi][f][3] + bvb; }
        }
    }
}

// ---------------------------------------------------------------------------
// Kernel 2: attention per (b, h) — fp32, 2x2 register tiling + float4 LDS.
// Arrays get one spare row (82) so 2-wide tiles never need clamping.
// ---------------------------------------------------------------------------
#define QP 68   // floats per Q/K/V row (17 float4, odd -> conflict-free)
#define SP 84   // floats per S row (21 float4, odd)
#define NROWS 82
#define SMEM_ATTN ((2 * NROWS * QP + NROWS * SP) * (int)sizeof(float))

__global__ __launch_bounds__(256) void attn_kernel(const float* __restrict__ rel_h,
                                                   const float* __restrict__ rel_w,
                                                   float* __restrict__ out) {
    extern __shared__ float sm[];
    float* Qs = sm;                      // [82][68]
    float* Ks = sm + NROWS * QP;         // [82][68], later reused as V
    float* S  = sm + 2 * NROWS * QP;     // [82][84]

    const int bh = blockIdx.x;
    const int b  = bh >> 3;
    const int h  = bh & 7;
    const int tid = threadIdx.x;

    const float* qkvb = g_qkv + (size_t)b * OC * NN;
    const float* Qg = qkvb + (size_t)(h * HD) * NN;
    const float* Kg = qkvb + (size_t)(DM + h * HD) * NN;
    const float* Vg = qkvb + (size_t)(2 * DM + h * HD) * NN;

    // Load Q (transpose to [n][d]) and Keff = K + rel_h + rel_w
    for (int idx = tid; idx < HD * NN; idx += 256) {
        int d = idx / NN;
        int n = idx % NN;
        Qs[n * QP + d] = Qg[d * NN + n];
        float rh = rel_h[(h * HD + d) * 9 + (n % 9)];
        float rw = rel_w[(h * HD + d) * 9 + (n / 9)];
        Ks[n * QP + d] = Kg[d * NN + n] + rh + rw;
    }
    __syncthreads();

    // Scores: 2x2 tiles, float4 dot over 64
    for (int t = tid; t < 41 * 41; t += 256) {
        int ti = t / 41;
        int tj = t - ti * 41;
        int n0 = 2 * ti;
        int m0 = 2 * tj;
        const float4* q0 = (const float4*)(Qs + n0 * QP);
        const float4* q1 = (const float4*)(Qs + (n0 + 1) * QP);
        const float4* k0 = (const float4*)(Ks + m0 * QP);
        const float4* k1 = (const float4*)(Ks + (m0 + 1) * QP);
        float s00 = 0.f, s01 = 0.f, s10 = 0.f, s11 = 0.f;
#pragma unroll
        for (int dv = 0; dv < 16; dv++) {
            float4 a0 = q0[dv], a1 = q1[dv], c0 = k0[dv], c1 = k1[dv];
            s00 += a0.x * c0.x + a0.y * c0.y + a0.z * c0.z + a0.w * c0.w;
            s01 += a0.x * c1.x + a0.y * c1.y + a0.z * c1.z + a0.w * c1.w;
            s10 += a1.x * c0.x + a1.y * c0.y + a1.z * c0.z + a1.w * c0.w;
            s11 += a1.x * c1.x + a1.y * c1.y + a1.z * c1.z + a1.w * c1.w;
        }
        S[n0 * SP + m0]           = s00;
        S[n0 * SP + m0 + 1]       = s01;
        S[(n0 + 1) * SP + m0]     = s10;
        S[(n0 + 1) * SP + m0 + 1] = s11;
    }
    __syncthreads();

    // Load V over Ks; softmax rows of S in-place
    for (int idx = tid; idx < HD * NN; idx += 256) {
        int d = idx / NN;
        int n = idx % NN;
        Ks[n * QP + d] = Vg[d * NN + n];
    }
    if (tid < NN) {
        float* row = S + tid * SP;
        float mx = row[0];
        for (int m = 1; m < NN; m++) mx = fmaxf(mx, row[m]);
        float sum = 0.0f;
        for (int m = 0; m < NN; m++) {
            float e = __expf(row[m] - mx);
            row[m] = e;
            sum += e;
        }
        float inv = 1.0f / sum;
        for (int m = 0; m < NN; m++) row[m] *= inv;
    }
    __syncthreads();

    // PV: tiles (2 n-rows) x (4 d-cols); V float4, P broadcast
    for (int t = tid; t < 41 * 16; t += 256) {
        int ti = t >> 4;
        int d4 = t & 15;
        int n0 = 2 * ti;
        const float* p0 = S + n0 * SP;
        const float* p1 = S + (n0 + 1) * SP;
        float4 a0 = make_float4(0.f, 0.f, 0.f, 0.f);
        float4 a1 = make_float4(0.f, 0.f, 0.f, 0.f);
        for (int m = 0; m < NN; m++) {
            float4 v = *(const float4*)(Ks + m * QP + 4 * d4);
            float w0 = p0[m], w1 = p1[m];
            a0.x += w0 * v.x; a0.y += w0 * v.y; a0.z += w0 * v.z; a0.w += w0 * v.w;
            a1.x += w1 * v.x; a1.y += w1 * v.y; a1.z += w1 * v.z; a1.w += w1 * v.w;
        }
        const int d = 4 * d4;
        float* o0 = out + ((size_t)b * DM + h * HD + d) * NN + n0;
        o0[0]          = a0.x;
        o0[NN]         = a0.y;
        o0[2 * NN]     = a0.z;
        o0[3 * NN]     = a0.w;
        if (n0 + 1 < NN) {
            o0[1]          = a1.x;
            o0[NN + 1]     = a1.y;
            o0[2 * NN + 1] = a1.z;
            o0[3 * NN + 1] = a1.w;
        }
    }
}

// ---------------------------------------------------------------------------
extern "C" void kernel_launch(void* const* d_in, const int* in_sizes, int n_in,
                              void* d_out, int out_size) {
    const float* x     = (const float*)d_in[0];
    const float* qkv_w = (const float*)d_in[1];
    const float* qkv_b = (const float*)d_in[2];
    const float* rel_h = (const float*)d_in[3];
    const float* rel_w = (const float*)d_in[4];
    float* out = (float*)d_out;

    cudaFuncSetAttribute(attn_kernel, cudaFuncAttributeMaxDynamicSharedMemorySize, SMEM_ATTN);
    cudaFuncSetAttribute(qkv_gemm_f16, cudaFuncAttributeMaxDynamicSharedMemorySize, SMEM_GEMM);

    prep_w<<<OC * DM / 256, 256>>>(qkv_w);
    prep_x<<<dim3(BB, DM / 64), 256>>>(x);
    qkv_gemm_f16<<<dim3(OC / MT, BB), 256, SMEM_GEMM>>>(qkv_b);
    attn_kernel<<<BB * NH, 256, SMEM_ATTN>>>(rel_h, rel_w, out);
}

// round 9
// speedup vs baseline: 3.7100x; 1.2119x over previous
#include <cuda_runtime.h>
#include <cuda_fp16.h>
#include <math.h>
#include <stdint.h>

// Problem constants
#define BB   1024
#define DM   512
#define NH   8
#define HD   64
#define NN   81
#define OC   1536

// Fused tiling: CTA = (b, h); A rows = 64 Q + 64 K + 64 V for head h
#define MT     192
#define NT     96            // padded n (81 -> 96)
#define KT     32            // k per pipeline stage (64B rows)
#define NTILES (DM / KT)     // 16
#define NSTG   2

#define RSTRIDE 80           // 64B data + 16B pad (ldmatrix conflict-free)
#define APL  (MT * RSTRIDE)             // 15360
#define BPL  (NT * RSTRIDE)             // 7680
#define STG_BYTES (APL + BPL)           // 23040
#define STAGES_BYTES (NSTG * STG_BYTES) // 46080

// attention smem planes
#define QP    68             // floats per Q/K/V row (17 float4)
#define SP    84             // floats per S row
#define NROWS 82
#define PLANE (NROWS * QP)   // 5576 floats
#define QKV_OFF STAGES_BYTES
#define SMEM_FUSED (QKV_OFF + 3 * PLANE * 4)   // 112992 B  -> 2 CTAs/SM

// Scratch (fp16 inputs only; no qkv round-trip)
__device__ __half g_wh[(size_t)OC * DM];
__device__ __half g_xh[(size_t)BB * NT * DM];

__device__ __forceinline__ uint32_t smem_u32(const void* p) {
    uint32_t a;
    asm("{ .reg .u64 t; cvta.to.shared.u64 t, %1; cvt.u32.u64 %0, t; }" : "=r"(a) : "l"(p));
    return a;
}

#define CP16(dst, src) \
    asm volatile("cp.async.cg.shared.global [%0], [%1], 16;" :: "r"(dst), "l"(src))
#define CP_COMMIT() asm volatile("cp.async.commit_group;" ::: "memory")
#define CP_WAIT(n)  asm volatile("cp.async.wait_group %0;" :: "n"(n) : "memory")

#define LDSM4(r0, r1, r2, r3, addr)                                           \
    asm volatile("ldmatrix.sync.aligned.m8n8.x4.shared.b16 {%0,%1,%2,%3}, [%4];" \
        : "=r"(r0), "=r"(r1), "=r"(r2), "=r"(r3) : "r"(addr))

#define MMA_F16(C, A, B)                                                      \
    asm volatile(                                                             \
        "mma.sync.aligned.m16n8k16.row.col.f32.f16.f16.f32 "                  \
        "{%0,%1,%2,%3}, {%4,%5,%6,%7}, {%8,%9}, {%0,%1,%2,%3};\n"             \
        : "+f"((C)[0]), "+f"((C)[1]), "+f"((C)[2]), "+f"((C)[3])              \
        : "r"((A)[0]), "r"((A)[1]), "r"((A)[2]), "r"((A)[3]),                 \
          "r"((B)[0]), "r"((B)[1]))

// ---------------------------------------------------------------------------
// Prep: W -> fp16 [o][c]
// ---------------------------------------------------------------------------
__global__ void prep_w(const float* __restrict__ w) {
    int i = blockIdx.x * 256 + threadIdx.x;
    g_wh[i] = __float2half_rn(w[i]);
}

// ---------------------------------------------------------------------------
// Prep: transpose X -> [b][n(96)][c(512)] fp16 (n>=81 zeroed)
// ---------------------------------------------------------------------------
__global__ __launch_bounds__(256) void prep_x(const float* __restrict__ x) {
    __shared__ float ts[64][83];
    const int b  = blockIdx.x;
    const int c0 = blockIdx.y * 64;
    const int tid = threadIdx.x;

    const float* xb = x + ((size_t)b * DM + c0) * NN;
    for (int idx = tid; idx < 64 * NN; idx += 256) {
        int c = idx / NN;
        int n = idx - c * NN;
        ts[c][n] = xb[(size_t)c * NN + n];
    }
    __syncthreads();

    for (int idx = tid; idx < NT * 64; idx += 256) {
        int n = idx >> 6;
        int c = idx & 63;
        float v = (n < NN) ? ts[c][n] : 0.0f;
        g_xh[((size_t)b * NT + n) * DM + c0 + c] = __float2half_rn(v);
    }
}

// ---------------------------------------------------------------------------
// Stage loader. A rows 0..191 map to W rows {h*64+r, 512+h*64+r, 1024+h*64+r}
// ---------------------------------------------------------------------------
__device__ __forceinline__ void load_stage(uint32_t sb, char* smem, int stage,
                                           int k0, int h64, int b, int tid) {
    const uint32_t base = sb + stage * STG_BYTES;
#pragma unroll
    for (int i = 0; i < 3; i++) {                // A: 768 chunks
        int idx = tid + i * 256;
        int row = idx >> 2;
        int chv = idx & 3;
        int o   = (row >> 6) * DM + h64 + (row & 63);
        const __half* src = g_wh + (size_t)o * DM + k0 + chv * 8;
        CP16(base + row * RSTRIDE + chv * 16, src);
    }
#pragma unroll
    for (int i = 0; i < 2; i++) {                // B: 384 chunks
        int idx = tid + i * 256;
        if (idx < 384) {
            int row = idx >> 2;
            int chv = idx & 3;
            const __half* src = g_xh + ((size_t)b * NT + row) * DM + k0 + chv * 8;
            CP16(base + APL + row * RSTRIDE + chv * 16, src);
        }
    }
    CP_COMMIT();
}

// ---------------------------------------------------------------------------
// Fused kernel: per (b,h) QKV projection (fp16 HMMA) + attention (fp32).
// 8 warps = 4(M: 48 rows) x 2(N: 48 cols); acc[3][6][4].
// ---------------------------------------------------------------------------
__global__ __launch_bounds__(256, 2) void fused_mhsa(const float* __restrict__ bias,
                                                     const float* __restrict__ rel_h,
                                                     const float* __restrict__ rel_w,
                                                     float* __restrict__ out) {
    extern __shared__ char smem[];
    const uint32_t sb = smem_u32(smem);
    float* Qs = (float*)(smem + QKV_OFF);     // [82][68]
    float* Ks = Qs + PLANE;
    float* Vs = Ks + PLANE;
    float* S  = (float*)smem;                 // aliases GEMM stages, [82][84]

    const int tid  = threadIdx.x;
    const int bh   = blockIdx.x;
    const int b    = bh >> 3;
    const int h    = bh & 7;
    const int h64  = h * HD;
    const int warp = tid >> 5;
    const int lane = tid & 31;
    const int wm   = warp & 3;
    const int wn   = warp >> 2;
    const int g    = lane >> 2;
    const int l4   = lane & 3;

    const uint32_t aoff = ((lane & 7) + ((lane >> 3) & 1) * 8) * RSTRIDE + (lane >> 4) * 16;
    const uint32_t boff = ((lane & 7) + ((lane >> 4) & 1) * 8) * RSTRIDE + ((lane >> 3) & 1) * 16;

    float acc[3][6][4];
#pragma unroll
    for (int i = 0; i < 3; i++)
#pragma unroll
        for (int j = 0; j < 6; j++)
#pragma unroll
            for (int r = 0; r < 4; r++) acc[i][j][r] = 0.0f;

    // ------------------- GEMM phase -------------------
    load_stage(sb, smem, 0, 0, h64, b, tid);
    load_stage(sb, smem, 1, KT, h64, b, tid);

    for (int ch = 0; ch < NTILES; ch++) {
        if (ch + 1 < NTILES) { CP_WAIT(1); } else { CP_WAIT(0); }
        __syncthreads();

        const uint32_t st = sb + (ch & 1) * STG_BYTES;
        const uint32_t sA = st;
        const uint32_t sB = st + APL;

#pragma unroll
        for (int ks = 0; ks < 2; ks++) {
            uint32_t a[3][4];
#pragma unroll
            for (int mi = 0; mi < 3; mi++) {
                uint32_t ra = (uint32_t)((wm * 48 + mi * 16) * RSTRIDE + ks * 32) + aoff;
                LDSM4(a[mi][0], a[mi][1], a[mi][2], a[mi][3], sA + ra);
            }
            uint32_t bf[3][4];
#pragma unroll
            for (int pr = 0; pr < 3; pr++) {
                uint32_t rb = (uint32_t)((wn * 48 + pr * 16) * RSTRIDE + ks * 32) + boff;
                LDSM4(bf[pr][0], bf[pr][1], bf[pr][2], bf[pr][3], sB + rb);
            }
#pragma unroll
            for (int pr = 0; pr < 3; pr++)
#pragma unroll
                for (int sub = 0; sub < 2; sub++)
#pragma unroll
                    for (int mi = 0; mi < 3; mi++)
                        MMA_F16(acc[mi][pr * 2 + sub], a[mi], bf[pr] + sub * 2);
        }

        if (ch + 2 < NTILES) {
            __syncthreads();   // all warps done reading buffer (ch&1) before refill
            load_stage(sb, smem, ch & 1, (ch + 2) * KT, h64, b, tid);
        }
    }

    // ---- Epilogue: accs -> smem planes, transposed [n][d]; bias + rel fold ----
#pragma unroll
    for (int mi = 0; mi < 3; mi++) {
#pragma unroll
        for (int rr = 0; rr < 2; rr++) {
            const int row = wm * 48 + mi * 16 + g + rr * 8;
            const int grp = row >> 6;
            const int d   = row & 63;
            const float bv = bias[grp * DM + h64 + d];
            float* plane = (grp == 0) ? Qs : (grp == 1) ? Ks : Vs;
#pragma unroll
            for (int f = 0; f < 6; f++) {
                const int n0 = wn * 48 + f * 8 + 2 * l4;
#pragma unroll
                for (int cc = 0; cc < 2; cc++) {
                    const int col = n0 + cc;
                    if (col < NN) {
                        float v = acc[mi][f][rr * 2 + cc] + bv;
                        if (grp == 1)
                            v += rel_h[(h64 + d) * 9 + col % 9]
                               + rel_w[(h64 + d) * 9 + col / 9];
                        plane[col * QP + d] = v;
                    }
                }
            }
        }
    }
    __syncthreads();

    // ------------------- Attention phase -------------------
    // Scores: 2x2 tiles, float4 dot over 64 (S overwrites GEMM stage smem)
    for (int t = tid; t < 41 * 41; t += 256) {
        int ti = t / 41;
        int tj = t - ti * 41;
        int n0 = 2 * ti;
        int m0 = 2 * tj;
        const float4* q0 = (const float4*)(Qs + n0 * QP);
        const float4* q1 = (const float4*)(Qs + (n0 + 1) * QP);
        const float4* k0 = (const float4*)(Ks + m0 * QP);
        const float4* k1 = (const float4*)(Ks + (m0 + 1) * QP);
        float s00 = 0.f, s01 = 0.f, s10 = 0.f, s11 = 0.f;
#pragma unroll
        for (int dv = 0; dv < 16; dv++) {
            float4 a0 = q0[dv], a1 = q1[dv], c0 = k0[dv], c1 = k1[dv];
            s00 += a0.x * c0.x + a0.y * c0.y + a0.z * c0.z + a0.w * c0.w;
            s01 += a0.x * c1.x + a0.y * c1.y + a0.z * c1.z + a0.w * c1.w;
            s10 += a1.x * c0.x + a1.y * c0.y + a1.z * c0.z + a1.w * c0.w;
            s11 += a1.x * c1.x + a1.y * c1.y + a1.z * c1.z + a1.w * c1.w;
        }
        S[n0 * SP + m0]           = s00;
        S[n0 * SP + m0 + 1]       = s01;
        S[(n0 + 1) * SP + m0]     = s10;
        S[(n0 + 1) * SP + m0 + 1] = s11;
    }
    __syncthreads();

    // softmax rows
    if (tid < NN) {
        float* row = S + tid * SP;
        float mx = row[0];
        for (int m = 1; m < NN; m++) mx = fmaxf(mx, row[m]);
        float sum = 0.0f;
        for (int m = 0; m < NN; m++) {
            float e = __expf(row[m] - mx);
            row[m] = e;
            sum += e;
        }
        float inv = 1.0f / sum;
        for (int m = 0; m < NN; m++) row[m] *= inv;
    }
    __syncthreads();

    // PV: (2 n-rows) x (4 d-cols) tiles; V float4
    for (int t = tid; t < 41 * 16; t += 256) {
        int ti = t >> 4;
        int d4 = t & 15;
        int n0 = 2 * ti;
        const float* p0 = S + n0 * SP;
        const float* p1 = S + (n0 + 1) * SP;
        float4 a0 = make_float4(0.f, 0.f, 0.f, 0.f);
        float4 a1 = make_float4(0.f, 0.f, 0.f, 0.f);
        for (int m = 0; m < NN; m++) {
            float4 v = *(const float4*)(Vs + m * QP + 4 * d4);
            float w0 = p0[m], w1 = p1[m];
            a0.x += w0 * v.x; a0.y += w0 * v.y; a0.z += w0 * v.z; a0.w += w0 * v.w;
            a1.x += w1 * v.x; a1.y += w1 * v.y; a1.z += w1 * v.z; a1.w += w1 * v.w;
        }
        const int d = 4 * d4;
        float* o0 = out + ((size_t)b * DM + h64 + d) * NN + n0;
        o0[0]          = a0.x;
        o0[NN]         = a0.y;
        o0[2 * NN]     = a0.z;
        o0[3 * NN]     = a0.w;
        if (n0 + 1 < NN) {
            o0[1]          = a1.x;
            o0[NN + 1]     = a1.y;
            o0[2 * NN + 1] = a1.z;
            o0[3 * NN + 1] = a1.w;
        }
    }
}

// ---------------------------------------------------------------------------
extern "C" void kernel_launch(void* const* d_in, const int* in_sizes, int n_in,
                              void* d_out, int out_size) {
    const float* x     = (const float*)d_in[0];
    const float* qkv_w = (const float*)d_in[1];
    const float* qkv_b = (const float*)d_in[2];
    const float* rel_h = (const float*)d_in[3];
    const float* rel_w = (const float*)d_in[4];
    float* out = (float*)d_out;

    cudaFuncSetAttribute(fused_mhsa, cudaFuncAttributeMaxDynamicSharedMemorySize, SMEM_FUSED);

    prep_w<<<OC * DM / 256, 256>>>(qkv_w);
    prep_x<<<dim3(BB, DM / 64), 256>>>(x);
    fused_mhsa<<<BB * NH, 256, SMEM_FUSED>>>(qkv_b, rel_h, rel_w, out);
}